// round 6
// baseline (speedup 1.0000x reference)
#include <cuda_runtime.h>

// CrossAttention: B=4, N=M=1024, DIM=1024, HEADS=16, HEAD_DIM=64, V_HEAD_DIM=64
//
// Pipeline (all fp32, all on default stream, graph-capturable):
//   1) proj_kernel<1024>: g_q  [4096,1024] = x   @ Wq
//   2) proj_kernel<2048>: g_kv [4096,2048] = ctx @ Wkv   (k = cols[0:1024], v = cols[1024:2048])
//   3) dots_kernel:  g_w[b,h,i,j] = 0.125 * sum_d q[b,i,h,d]*k[b,j,h,d]   (batched NT gemm)
//   4) softmax_kernel: row softmax over j (warp per row)
//   5) talking_kernel: 16x16 head mix + LayerNorm over heads, in place on g_w
//   6) attnv_kernel: out[b,i,h*64+vd] = sum_j g_w[b,h,i,j] * v[b,j,h,vd]  (batched NN gemm)

static constexpr int B_   = 4;
static constexpr int N_   = 1024;
static constexpr int M_   = 1024;
static constexpr int DIM_ = 1024;
static constexpr int H_   = 16;
static constexpr size_t NM_ = (size_t)N_ * M_;   // 1<<20

// Scratch (device globals: allocation-free, allowed by harness rules)
__device__ float g_q [(size_t)B_ * N_ * DIM_];          // [b*N+n][h*64+d]      16 MB
__device__ float g_kv[(size_t)B_ * M_ * 2 * DIM_];      // [b*M+m][0:1024 k, 1024:2048 v]  32 MB
__device__ float g_w [(size_t)B_ * H_ * N_ * M_];       // [((b*16+h)*N+i)*M+j] 256 MB

// ---------------------------------------------------------------------------
// Kernel 1/2: C[4096, NCOLS] = A[4096,1024] @ Bw[1024, NCOLS]
// Classic 128x128x8 double-buffered SGEMM, 256 threads, 8x8 micro-tile.
// ---------------------------------------------------------------------------
template<int NCOLS>
__global__ __launch_bounds__(256, 2)
void proj_kernel(const float* __restrict__ A, const float* __restrict__ Bw) {
    float* __restrict__ C = (NCOLS == 1024) ? g_q : g_kv;
    constexpr int K  = 1024;
    constexpr int NT = K / 8;
    constexpr int AS = 132;                 // padded row stride for As (bank-spread, 16B-aligned)
    __shared__ float As[2][8 * AS];
    __shared__ float Bs[2][8 * 128];

    const int tid  = threadIdx.x;
    const int brow = blockIdx.y * 128;
    const int bcol = blockIdx.x * 128;

    const int arow = tid >> 1;
    const int acol = (tid & 1) * 4;
    const int brw  = tid >> 5;
    const int bcl  = (tid & 31) * 4;

    const float* Ap = A  + (size_t)(brow + arow) * K + acol;
    const float* Bp = Bw + (size_t)brw * NCOLS + bcol + bcl;

    const int tx = tid & 15;
    const int ty = tid >> 4;

    float acc[8][8];
#pragma unroll
    for (int i = 0; i < 8; ++i)
#pragma unroll
        for (int j = 0; j < 8; ++j) acc[i][j] = 0.f;

    float4 a_reg = *(const float4*)(Ap);
    float4 b_reg = *(const float4*)(Bp);
    int buf = 0;
    As[0][(acol + 0) * AS + arow] = a_reg.x;
    As[0][(acol + 1) * AS + arow] = a_reg.y;
    As[0][(acol + 2) * AS + arow] = a_reg.z;
    As[0][(acol + 3) * AS + arow] = a_reg.w;
    *(float4*)&Bs[0][brw * 128 + bcl] = b_reg;
    __syncthreads();

    for (int kt = 0; kt < NT; ++kt) {
        if (kt + 1 < NT) {
            a_reg = *(const float4*)(Ap + (kt + 1) * 8);
            b_reg = *(const float4*)(Bp + (size_t)(kt + 1) * 8 * NCOLS);
        }
#pragma unroll
        for (int k = 0; k < 8; ++k) {
            float4 a0 = *(const float4*)&As[buf][k * AS + ty * 4];
            float4 a1 = *(const float4*)&As[buf][k * AS + 64 + ty * 4];
            float4 b0 = *(const float4*)&Bs[buf][k * 128 + tx * 4];
            float4 b1 = *(const float4*)&Bs[buf][k * 128 + 64 + tx * 4];
            float ar[8] = {a0.x, a0.y, a0.z, a0.w, a1.x, a1.y, a1.z, a1.w};
            float br[8] = {b0.x, b0.y, b0.z, b0.w, b1.x, b1.y, b1.z, b1.w};
#pragma unroll
            for (int i = 0; i < 8; ++i)
#pragma unroll
                for (int j = 0; j < 8; ++j)
                    acc[i][j] = fmaf(ar[i], br[j], acc[i][j]);
        }
        if (kt + 1 < NT) {
            buf ^= 1;
            As[buf][(acol + 0) * AS + arow] = a_reg.x;
            As[buf][(acol + 1) * AS + arow] = a_reg.y;
            As[buf][(acol + 2) * AS + arow] = a_reg.z;
            As[buf][(acol + 3) * AS + arow] = a_reg.w;
            *(float4*)&Bs[buf][brw * 128 + bcl] = b_reg;
            __syncthreads();
        }
    }

#pragma unroll
    for (int ih = 0; ih < 2; ++ih)
#pragma unroll
        for (int i = 0; i < 4; ++i) {
            const int r = brow + ih * 64 + ty * 4 + i;
            float* Cp = C + (size_t)r * NCOLS + bcol;
            *(float4*)(Cp + tx * 4) = make_float4(acc[ih * 4 + i][0], acc[ih * 4 + i][1],
                                                  acc[ih * 4 + i][2], acc[ih * 4 + i][3]);
            *(float4*)(Cp + 64 + tx * 4) = make_float4(acc[ih * 4 + i][4], acc[ih * 4 + i][5],
                                                       acc[ih * 4 + i][6], acc[ih * 4 + i][7]);
        }
}

// ---------------------------------------------------------------------------
// Kernel 3: batched NT gemm. Per (b,h): W[1024,1024] = 0.125 * Q[1024,64] @ K[1024,64]^T
// grid (M/128, N/128, B*H)
// ---------------------------------------------------------------------------
__global__ __launch_bounds__(256, 2)
void dots_kernel() {
    constexpr int NT = 64 / 8;   // 8 k-tiles over head_dim
    constexpr int AS = 132;
    __shared__ float As[2][8 * AS];
    __shared__ float Bs[2][8 * AS];

    const int tid  = threadIdx.x;
    const int z    = blockIdx.z;
    const int b    = z >> 4;
    const int h    = z & 15;
    const int brow = blockIdx.y * 128;
    const int bcol = blockIdx.x * 128;

    const int arow = tid >> 1;
    const int acol = (tid & 1) * 4;
    const float* Ap = g_q  + (size_t)b * N_ * DIM_ + h * 64 + (size_t)(brow + arow) * DIM_ + acol;
    const float* Bp = g_kv + (size_t)b * M_ * 2048 + h * 64 + (size_t)(bcol + arow) * 2048 + acol;
    float* Cbase = g_w + (size_t)z * NM_;

    const int tx = tid & 15;
    const int ty = tid >> 4;

    float acc[8][8];
#pragma unroll
    for (int i = 0; i < 8; ++i)
#pragma unroll
        for (int j = 0; j < 8; ++j) acc[i][j] = 0.f;

    float4 a_reg = *(const float4*)(Ap);
    float4 b_reg = *(const float4*)(Bp);
    int buf = 0;
    As[0][(acol + 0) * AS + arow] = a_reg.x;
    As[0][(acol + 1) * AS + arow] = a_reg.y;
    As[0][(acol + 2) * AS + arow] = a_reg.z;
    As[0][(acol + 3) * AS + arow] = a_reg.w;
    Bs[0][(acol + 0) * AS + arow] = b_reg.x;
    Bs[0][(acol + 1) * AS + arow] = b_reg.y;
    Bs[0][(acol + 2) * AS + arow] = b_reg.z;
    Bs[0][(acol + 3) * AS + arow] = b_reg.w;
    __syncthreads();

    for (int kt = 0; kt < NT; ++kt) {
        if (kt + 1 < NT) {
            a_reg = *(const float4*)(Ap + (kt + 1) * 8);
            b_reg = *(const float4*)(Bp + (kt + 1) * 8);
        }
#pragma unroll
        for (int k = 0; k < 8; ++k) {
            float4 a0 = *(const float4*)&As[buf][k * AS + ty * 4];
            float4 a1 = *(const float4*)&As[buf][k * AS + 64 + ty * 4];
            float4 b0 = *(const float4*)&Bs[buf][k * AS + tx * 4];
            float4 b1 = *(const float4*)&Bs[buf][k * AS + 64 + tx * 4];
            float ar[8] = {a0.x, a0.y, a0.z, a0.w, a1.x, a1.y, a1.z, a1.w};
            float br[8] = {b0.x, b0.y, b0.z, b0.w, b1.x, b1.y, b1.z, b1.w};
#pragma unroll
            for (int i = 0; i < 8; ++i)
#pragma unroll
                for (int j = 0; j < 8; ++j)
                    acc[i][j] = fmaf(ar[i], br[j], acc[i][j]);
        }
        if (kt + 1 < NT) {
            buf ^= 1;
            As[buf][(acol + 0) * AS + arow] = a_reg.x;
            As[buf][(acol + 1) * AS + arow] = a_reg.y;
            As[buf][(acol + 2) * AS + arow] = a_reg.z;
            As[buf][(acol + 3) * AS + arow] = a_reg.w;
            Bs[buf][(acol + 0) * AS + arow] = b_reg.x;
            Bs[buf][(acol + 1) * AS + arow] = b_reg.y;
            Bs[buf][(acol + 2) * AS + arow] = b_reg.z;
            Bs[buf][(acol + 3) * AS + arow] = b_reg.w;
            __syncthreads();
        }
    }

    const float scale = 0.125f;   // HEAD_DIM ** -0.5
#pragma unroll
    for (int ih = 0; ih < 2; ++ih)
#pragma unroll
        for (int i = 0; i < 4; ++i) {
            const int r = brow + ih * 64 + ty * 4 + i;
            float* Cp = Cbase + (size_t)r * M_ + bcol;
            const int ai = ih * 4 + i;
            *(float4*)(Cp + tx * 4) = make_float4(acc[ai][0] * scale, acc[ai][1] * scale,
                                                  acc[ai][2] * scale, acc[ai][3] * scale);
            *(float4*)(Cp + 64 + tx * 4) = make_float4(acc[ai][4] * scale, acc[ai][5] * scale,
                                                       acc[ai][6] * scale, acc[ai][7] * scale);
        }
}

// ---------------------------------------------------------------------------
// Kernel 4: softmax over last dim (1024) of g_w. One warp per row, 8 rows/block.
// ---------------------------------------------------------------------------
__global__ __launch_bounds__(256)
void softmax_kernel() {
    const int row  = blockIdx.x * 8 + (threadIdx.x >> 5);
    const int lane = threadIdx.x & 31;
    float* p = g_w + (size_t)row * 1024;

    float4 v[8];
    float mx = -1e30f;
#pragma unroll
    for (int i = 0; i < 8; ++i) {
        v[i] = *(const float4*)(p + i * 128 + lane * 4);
        mx = fmaxf(mx, fmaxf(fmaxf(v[i].x, v[i].y), fmaxf(v[i].z, v[i].w)));
    }
#pragma unroll
    for (int o = 16; o; o >>= 1) mx = fmaxf(mx, __shfl_xor_sync(0xffffffffu, mx, o));

    float s = 0.f;
#pragma unroll
    for (int i = 0; i < 8; ++i) {
        v[i].x = __expf(v[i].x - mx); s += v[i].x;
        v[i].y = __expf(v[i].y - mx); s += v[i].y;
        v[i].z = __expf(v[i].z - mx); s += v[i].z;
        v[i].w = __expf(v[i].w - mx); s += v[i].w;
    }
#pragma unroll
    for (int o = 16; o; o >>= 1) s += __shfl_xor_sync(0xffffffffu, s, o);
    const float r = 1.f / s;

#pragma unroll
    for (int i = 0; i < 8; ++i)
        *(float4*)(p + i * 128 + lane * 4) =
            make_float4(v[i].x * r, v[i].y * r, v[i].z * r, v[i].w * r);
}

// ---------------------------------------------------------------------------
// Kernel 5: talking heads (16x16 mix over h) + LayerNorm over heads, in place.
// One thread per (b,i,j); reads/writes 16 values strided by N*M.
// ---------------------------------------------------------------------------
__global__ __launch_bounds__(256)
void talking_kernel(const float* __restrict__ Wt,
                    const float* __restrict__ gamma,
                    const float* __restrict__ beta) {
    __shared__ float sWt[256];
    __shared__ float sg[16], sb[16];
    const int t = threadIdx.x;
    sWt[t] = Wt[t];
    if (t < 16) { sg[t] = gamma[t]; sb[t] = beta[t]; }
    __syncthreads();

    const size_t idx = (size_t)blockIdx.x * 256 + t;     // b*NM + i*M + j
    const int bb = (int)(idx >> 20);                     // NM = 2^20
    const size_t rem = idx & (NM_ - 1);
    float* base = g_w + (size_t)bb * 16 * NM_ + rem;

    float wv[16];
#pragma unroll
    for (int hh = 0; hh < 16; ++hh) wv[hh] = base[(size_t)hh * NM_];

    float o[16];
#pragma unroll
    for (int g = 0; g < 16; ++g) o[g] = 0.f;
#pragma unroll
    for (int hh = 0; hh < 16; ++hh) {
        const float v = wv[hh];
#pragma unroll
        for (int g = 0; g < 16; ++g) o[g] = fmaf(v, sWt[hh * 16 + g], o[g]);
    }

    float mu = 0.f;
#pragma unroll
    for (int g = 0; g < 16; ++g) mu += o[g];
    mu *= (1.f / 16.f);
    float var = 0.f;
#pragma unroll
    for (int g = 0; g < 16; ++g) { const float d = o[g] - mu; var = fmaf(d, d, var); }
    var *= (1.f / 16.f);
    const float rstd = rsqrtf(var + 1e-5f);

#pragma unroll
    for (int g = 0; g < 16; ++g)
        base[(size_t)g * NM_] = (o[g] - mu) * rstd * sg[g] + sb[g];
}

// ---------------------------------------------------------------------------
// Kernel 6: batched NN gemm. Per (b,h): out[1024,64] = W[1024,1024] @ V[1024,64]
// Output written directly into d_out[b, i, h*64 + vd]. grid (1, 8, 64).
// ---------------------------------------------------------------------------
__global__ __launch_bounds__(256, 2)
void attnv_kernel(float* __restrict__ out) {
    constexpr int NT = 1024 / 8;
    constexpr int AS = 132;
    __shared__ float As[2][8 * AS];
    __shared__ float Bs[2][8 * 64];

    const int tid  = threadIdx.x;
    const int z    = blockIdx.z;
    const int b    = z >> 4;
    const int h    = z & 15;
    const int brow = blockIdx.y * 128;

    const int arow = tid >> 1;
    const int acol = (tid & 1) * 4;
    const float* Ap = g_w + (size_t)z * NM_ + (size_t)(brow + arow) * 1024 + acol;
    const int vrow = tid >> 5;
    const int vcl  = (tid & 31) * 2;
    const float* Bp = g_kv + (size_t)b * M_ * 2048 + 1024 + h * 64 + (size_t)vrow * 2048 + vcl;

    const int tx = tid & 15;
    const int ty = tid >> 4;

    float acc[8][4];
#pragma unroll
    for (int i = 0; i < 8; ++i)
#pragma unroll
        for (int j = 0; j < 4; ++j) acc[i][j] = 0.f;

    float4 a_reg = *(const float4*)(Ap);
    float2 b_reg = *(const float2*)(Bp);
    int buf = 0;
    As[0][(acol + 0) * AS + arow] = a_reg.x;
    As[0][(acol + 1) * AS + arow] = a_reg.y;
    As[0][(acol + 2) * AS + arow] = a_reg.z;
    As[0][(acol + 3) * AS + arow] = a_reg.w;
    *(float2*)&Bs[0][vrow * 64 + vcl] = b_reg;
    __syncthreads();

    for (int kt = 0; kt < NT; ++kt) {
        if (kt + 1 < NT) {
            a_reg = *(const float4*)(Ap + (kt + 1) * 8);
            b_reg = *(const float2*)(Bp + (size_t)(kt + 1) * 8 * 2048);
        }
#pragma unroll
        for (int k = 0; k < 8; ++k) {
            float4 a0 = *(const float4*)&As[buf][k * AS + ty * 4];
            float4 a1 = *(const float4*)&As[buf][k * AS + 64 + ty * 4];
            float4 b0 = *(const float4*)&Bs[buf][k * 64 + tx * 4];
            float ar[8] = {a0.x, a0.y, a0.z, a0.w, a1.x, a1.y, a1.z, a1.w};
#pragma unroll
            for (int i = 0; i < 8; ++i) {
                acc[i][0] = fmaf(ar[i], b0.x, acc[i][0]);
                acc[i][1] = fmaf(ar[i], b0.y, acc[i][1]);
                acc[i][2] = fmaf(ar[i], b0.z, acc[i][2]);
                acc[i][3] = fmaf(ar[i], b0.w, acc[i][3]);
            }
        }
        if (kt + 1 < NT) {
            buf ^= 1;
            As[buf][(acol + 0) * AS + arow] = a_reg.x;
            As[buf][(acol + 1) * AS + arow] = a_reg.y;
            As[buf][(acol + 2) * AS + arow] = a_reg.z;
            As[buf][(acol + 3) * AS + arow] = a_reg.w;
            *(float2*)&Bs[buf][vrow * 64 + vcl] = b_reg;
            __syncthreads();
        }
    }

#pragma unroll
    for (int ih = 0; ih < 2; ++ih)
#pragma unroll
        for (int i = 0; i < 4; ++i) {
            const int r = brow + ih * 64 + ty * 4 + i;
            float* Cp = out + (size_t)(b * 1024 + r) * 1024 + h * 64 + tx * 4;
            const int ai = ih * 4 + i;
            *(float4*)Cp = make_float4(acc[ai][0], acc[ai][1], acc[ai][2], acc[ai][3]);
        }
}

// ---------------------------------------------------------------------------
extern "C" void kernel_launch(void* const* d_in, const int* in_sizes, int n_in,
                              void* d_out, int out_size) {
    (void)in_sizes; (void)n_in; (void)out_size;
    const float* x     = (const float*)d_in[0];
    const float* ctx   = (const float*)d_in[1];
    const float* Wq    = (const float*)d_in[2];
    const float* Wkv   = (const float*)d_in[3];
    const float* Wt    = (const float*)d_in[4];
    const float* gamma = (const float*)d_in[5];
    const float* beta  = (const float*)d_in[6];
    float* out = (float*)d_out;

    proj_kernel<1024><<<dim3(1024 / 128, (B_ * N_) / 128), 256>>>(x, Wq);
    proj_kernel<2048><<<dim3(2048 / 128, (B_ * M_) / 128), 256>>>(ctx, Wkv);
    dots_kernel<<<dim3(M_ / 128, N_ / 128, B_ * H_), 256>>>();
    softmax_kernel<<<(B_ * H_ * N_) / 8, 256>>>();
    talking_kernel<<<(unsigned)((B_ * NM_) / 256), 256>>>(Wt, gamma, beta);
    attnv_kernel<<<dim3(1, N_ / 128, B_ * H_), 256>>>(out);
}

// round 7
// speedup vs baseline: 1.0006x; 1.0006x over previous
#include <cuda_runtime.h>

// CrossAttention: B=4, N=M=1024, DIM=1024, HEADS=16, HEAD_DIM=64, V_HEAD_DIM=64
//
// Pipeline (all fp32, all on default stream, graph-capturable):
//   1) proj_kernel<1024>: g_q  [4096,1024] = x   @ Wq
//   2) proj_kernel<2048>: g_kv [4096,2048] = ctx @ Wkv   (k = cols[0:1024], v = cols[1024:2048])
//   3) dots_kernel:  g_w[b,h,i,j] = 0.125 * sum_d q[b,i,h,d]*k[b,j,h,d]   (batched NT gemm)
//   4) softmax_kernel: row softmax over j (warp per row)
//   5) talking_kernel: 16x16 head mix + LayerNorm over heads, in place on g_w
//   6) attnv_kernel: out[b,i,h*64+vd] = sum_j g_w[b,h,i,j] * v[b,j,h,vd]  (batched NN gemm)

static constexpr int B_   = 4;
static constexpr int N_   = 1024;
static constexpr int M_   = 1024;
static constexpr int DIM_ = 1024;
static constexpr int H_   = 16;
static constexpr size_t NM_ = (size_t)N_ * M_;   // 1<<20

// Scratch (device globals: allocation-free, allowed by harness rules)
__device__ float g_q [(size_t)B_ * N_ * DIM_];          // [b*N+n][h*64+d]      16 MB
__device__ float g_kv[(size_t)B_ * M_ * 2 * DIM_];      // [b*M+m][0:1024 k, 1024:2048 v]  32 MB
__device__ float g_w [(size_t)B_ * H_ * N_ * M_];       // [((b*16+h)*N+i)*M+j] 256 MB

// ---------------------------------------------------------------------------
// Kernel 1/2: C[4096, NCOLS] = A[4096,1024] @ Bw[1024, NCOLS]
// Classic 128x128x8 double-buffered SGEMM, 256 threads, 8x8 micro-tile.
// ---------------------------------------------------------------------------
template<int NCOLS>
__global__ __launch_bounds__(256, 2)
void proj_kernel(const float* __restrict__ A, const float* __restrict__ Bw) {
    float* __restrict__ C = (NCOLS == 1024) ? g_q : g_kv;
    constexpr int K  = 1024;
    constexpr int NT = K / 8;
    constexpr int AS = 132;                 // padded row stride for As (bank-spread, 16B-aligned)
    __shared__ float As[2][8 * AS];
    __shared__ float Bs[2][8 * 128];

    const int tid  = threadIdx.x;
    const int brow = blockIdx.y * 128;
    const int bcol = blockIdx.x * 128;

    const int arow = tid >> 1;
    const int acol = (tid & 1) * 4;
    const int brw  = tid >> 5;
    const int bcl  = (tid & 31) * 4;

    const float* Ap = A  + (size_t)(brow + arow) * K + acol;
    const float* Bp = Bw + (size_t)brw * NCOLS + bcol + bcl;

    const int tx = tid & 15;
    const int ty = tid >> 4;

    float acc[8][8];
#pragma unroll
    for (int i = 0; i < 8; ++i)
#pragma unroll
        for (int j = 0; j < 8; ++j) acc[i][j] = 0.f;

    float4 a_reg = *(const float4*)(Ap);
    float4 b_reg = *(const float4*)(Bp);
    int buf = 0;
    As[0][(acol + 0) * AS + arow] = a_reg.x;
    As[0][(acol + 1) * AS + arow] = a_reg.y;
    As[0][(acol + 2) * AS + arow] = a_reg.z;
    As[0][(acol + 3) * AS + arow] = a_reg.w;
    *(float4*)&Bs[0][brw * 128 + bcl] = b_reg;
    __syncthreads();

    for (int kt = 0; kt < NT; ++kt) {
        if (kt + 1 < NT) {
            a_reg = *(const float4*)(Ap + (kt + 1) * 8);
            b_reg = *(const float4*)(Bp + (size_t)(kt + 1) * 8 * NCOLS);
        }
#pragma unroll
        for (int k = 0; k < 8; ++k) {
            float4 a0 = *(const float4*)&As[buf][k * AS + ty * 4];
            float4 a1 = *(const float4*)&As[buf][k * AS + 64 + ty * 4];
            float4 b0 = *(const float4*)&Bs[buf][k * 128 + tx * 4];
            float4 b1 = *(const float4*)&Bs[buf][k * 128 + 64 + tx * 4];
            float ar[8] = {a0.x, a0.y, a0.z, a0.w, a1.x, a1.y, a1.z, a1.w};
            float br[8] = {b0.x, b0.y, b0.z, b0.w, b1.x, b1.y, b1.z, b1.w};
#pragma unroll
            for (int i = 0; i < 8; ++i)
#pragma unroll
                for (int j = 0; j < 8; ++j)
                    acc[i][j] = fmaf(ar[i], br[j], acc[i][j]);
        }
        if (kt + 1 < NT) {
            buf ^= 1;
            As[buf][(acol + 0) * AS + arow] = a_reg.x;
            As[buf][(acol + 1) * AS + arow] = a_reg.y;
            As[buf][(acol + 2) * AS + arow] = a_reg.z;
            As[buf][(acol + 3) * AS + arow] = a_reg.w;
            *(float4*)&Bs[buf][brw * 128 + bcl] = b_reg;
            __syncthreads();
        }
    }

#pragma unroll
    for (int ih = 0; ih < 2; ++ih)
#pragma unroll
        for (int i = 0; i < 4; ++i) {
            const int r = brow + ih * 64 + ty * 4 + i;
            float* Cp = C + (size_t)r * NCOLS + bcol;
            *(float4*)(Cp + tx * 4) = make_float4(acc[ih * 4 + i][0], acc[ih * 4 + i][1],
                                                  acc[ih * 4 + i][2], acc[ih * 4 + i][3]);
            *(float4*)(Cp + 64 + tx * 4) = make_float4(acc[ih * 4 + i][4], acc[ih * 4 + i][5],
                                                       acc[ih * 4 + i][6], acc[ih * 4 + i][7]);
        }
}

// ---------------------------------------------------------------------------
// Kernel 3: batched NT gemm. Per (b,h): W[1024,1024] = 0.125 * Q[1024,64] @ K[1024,64]^T
// grid (M/128, N/128, B*H)
// ---------------------------------------------------------------------------
__global__ __launch_bounds__(256, 2)
void dots_kernel() {
    constexpr int NT = 64 / 8;   // 8 k-tiles over head_dim
    constexpr int AS = 132;
    __shared__ float As[2][8 * AS];
    __shared__ float Bs[2][8 * AS];

    const int tid  = threadIdx.x;
    const int z    = blockIdx.z;
    const int b    = z >> 4;
    const int h    = z & 15;
    const int brow = blockIdx.y * 128;
    const int bcol = blockIdx.x * 128;

    const int arow = tid >> 1;
    const int acol = (tid & 1) * 4;
    const float* Ap = g_q  + (size_t)b * N_ * DIM_ + h * 64 + (size_t)(brow + arow) * DIM_ + acol;
    const float* Bp = g_kv + (size_t)b * M_ * 2048 + h * 64 + (size_t)(bcol + arow) * 2048 + acol;
    float* Cbase = g_w + (size_t)z * NM_;

    const int tx = tid & 15;
    const int ty = tid >> 4;

    float acc[8][8];
#pragma unroll
    for (int i = 0; i < 8; ++i)
#pragma unroll
        for (int j = 0; j < 8; ++j) acc[i][j] = 0.f;

    float4 a_reg = *(const float4*)(Ap);
    float4 b_reg = *(const float4*)(Bp);
    int buf = 0;
    As[0][(acol + 0) * AS + arow] = a_reg.x;
    As[0][(acol + 1) * AS + arow] = a_reg.y;
    As[0][(acol + 2) * AS + arow] = a_reg.z;
    As[0][(acol + 3) * AS + arow] = a_reg.w;
    Bs[0][(acol + 0) * AS + arow] = b_reg.x;
    Bs[0][(acol + 1) * AS + arow] = b_reg.y;
    Bs[0][(acol + 2) * AS + arow] = b_reg.z;
    Bs[0][(acol + 3) * AS + arow] = b_reg.w;
    __syncthreads();

    for (int kt = 0; kt < NT; ++kt) {
        if (kt + 1 < NT) {
            a_reg = *(const float4*)(Ap + (kt + 1) * 8);
            b_reg = *(const float4*)(Bp + (kt + 1) * 8);
        }
#pragma unroll
        for (int k = 0; k < 8; ++k) {
            float4 a0 = *(const float4*)&As[buf][k * AS + ty * 4];
            float4 a1 = *(const float4*)&As[buf][k * AS + 64 + ty * 4];
            float4 b0 = *(const float4*)&Bs[buf][k * AS + tx * 4];
            float4 b1 = *(const float4*)&Bs[buf][k * AS + 64 + tx * 4];
            float ar[8] = {a0.x, a0.y, a0.z, a0.w, a1.x, a1.y, a1.z, a1.w};
            float br[8] = {b0.x, b0.y, b0.z, b0.w, b1.x, b1.y, b1.z, b1.w};
#pragma unroll
            for (int i = 0; i < 8; ++i)
#pragma unroll
                for (int j = 0; j < 8; ++j)
                    acc[i][j] = fmaf(ar[i], br[j], acc[i][j]);
        }
        if (kt + 1 < NT) {
            buf ^= 1;
            As[buf][(acol + 0) * AS + arow] = a_reg.x;
            As[buf][(acol + 1) * AS + arow] = a_reg.y;
            As[buf][(acol + 2) * AS + arow] = a_reg.z;
            As[buf][(acol + 3) * AS + arow] = a_reg.w;
            Bs[buf][(acol + 0) * AS + arow] = b_reg.x;
            Bs[buf][(acol + 1) * AS + arow] = b_reg.y;
            Bs[buf][(acol + 2) * AS + arow] = b_reg.z;
            Bs[buf][(acol + 3) * AS + arow] = b_reg.w;
            __syncthreads();
        }
    }

    const float scale = 0.125f;   // HEAD_DIM ** -0.5
#pragma unroll
    for (int ih = 0; ih < 2; ++ih)
#pragma unroll
        for (int i = 0; i < 4; ++i) {
            const int r = brow + ih * 64 + ty * 4 + i;
            float* Cp = Cbase + (size_t)r * M_ + bcol;
            const int ai = ih * 4 + i;
            *(float4*)(Cp + tx * 4) = make_float4(acc[ai][0] * scale, acc[ai][1] * scale,
                                                  acc[ai][2] * scale, acc[ai][3] * scale);
            *(float4*)(Cp + 64 + tx * 4) = make_float4(acc[ai][4] * scale, acc[ai][5] * scale,
                                                       acc[ai][6] * scale, acc[ai][7] * scale);
        }
}

// ---------------------------------------------------------------------------
// Kernel 4: softmax over last dim (1024) of g_w. One warp per row, 8 rows/block.
// ---------------------------------------------------------------------------
__global__ __launch_bounds__(256)
void softmax_kernel() {
    const int row  = blockIdx.x * 8 + (threadIdx.x >> 5);
    const int lane = threadIdx.x & 31;
    float* p = g_w + (size_t)row * 1024;

    float4 v[8];
    float mx = -1e30f;
#pragma unroll
    for (int i = 0; i < 8; ++i) {
        v[i] = *(const float4*)(p + i * 128 + lane * 4);
        mx = fmaxf(mx, fmaxf(fmaxf(v[i].x, v[i].y), fmaxf(v[i].z, v[i].w)));
    }
#pragma unroll
    for (int o = 16; o; o >>= 1) mx = fmaxf(mx, __shfl_xor_sync(0xffffffffu, mx, o));

    float s = 0.f;
#pragma unroll
    for (int i = 0; i < 8; ++i) {
        v[i].x = __expf(v[i].x - mx); s += v[i].x;
        v[i].y = __expf(v[i].y - mx); s += v[i].y;
        v[i].z = __expf(v[i].z - mx); s += v[i].z;
        v[i].w = __expf(v[i].w - mx); s += v[i].w;
    }
#pragma unroll
    for (int o = 16; o; o >>= 1) s += __shfl_xor_sync(0xffffffffu, s, o);
    const float r = 1.f / s;

#pragma unroll
    for (int i = 0; i < 8; ++i)
        *(float4*)(p + i * 128 + lane * 4) =
            make_float4(v[i].x * r, v[i].y * r, v[i].z * r, v[i].w * r);
}

// ---------------------------------------------------------------------------
// Kernel 5: talking heads (16x16 mix over h) + LayerNorm over heads, in place.
// One thread per (b,i,j); reads/writes 16 values strided by N*M.
// ---------------------------------------------------------------------------
__global__ __launch_bounds__(256)
void talking_kernel(const float* __restrict__ Wt,
                    const float* __restrict__ gamma,
                    const float* __restrict__ beta) {
    __shared__ float sWt[256];
    __shared__ float sg[16], sb[16];
    const int t = threadIdx.x;
    sWt[t] = Wt[t];
    if (t < 16) { sg[t] = gamma[t]; sb[t] = beta[t]; }
    __syncthreads();

    const size_t idx = (size_t)blockIdx.x * 256 + t;     // b*NM + i*M + j
    const int bb = (int)(idx >> 20);                     // NM = 2^20
    const size_t rem = idx & (NM_ - 1);
    float* base = g_w + (size_t)bb * 16 * NM_ + rem;

    float wv[16];
#pragma unroll
    for (int hh = 0; hh < 16; ++hh) wv[hh] = base[(size_t)hh * NM_];

    float o[16];
#pragma unroll
    for (int g = 0; g < 16; ++g) o[g] = 0.f;
#pragma unroll
    for (int hh = 0; hh < 16; ++hh) {
        const float v = wv[hh];
#pragma unroll
        for (int g = 0; g < 16; ++g) o[g] = fmaf(v, sWt[hh * 16 + g], o[g]);
    }

    float mu = 0.f;
#pragma unroll
    for (int g = 0; g < 16; ++g) mu += o[g];
    mu *= (1.f / 16.f);
    float var = 0.f;
#pragma unroll
    for (int g = 0; g < 16; ++g) { const float d = o[g] - mu; var = fmaf(d, d, var); }
    var *= (1.f / 16.f);
    const float rstd = rsqrtf(var + 1e-5f);

#pragma unroll
    for (int g = 0; g < 16; ++g)
        base[(size_t)g * NM_] = (o[g] - mu) * rstd * sg[g] + sb[g];
}

// ---------------------------------------------------------------------------
// Kernel 6: batched NN gemm. Per (b,h): out[1024,64] = W[1024,1024] @ V[1024,64]
// Output written directly into d_out[b, i, h*64 + vd]. grid (1, 8, 64).
// ---------------------------------------------------------------------------
__global__ __launch_bounds__(256, 2)
void attnv_kernel(float* __restrict__ out) {
    constexpr int NT = 1024 / 8;
    constexpr int AS = 132;
    __shared__ float As[2][8 * AS];
    __shared__ float Bs[2][8 * 64];

    const int tid  = threadIdx.x;
    const int z    = blockIdx.z;
    const int b    = z >> 4;
    const int h    = z & 15;
    const int brow = blockIdx.y * 128;

    const int arow = tid >> 1;
    const int acol = (tid & 1) * 4;
    const float* Ap = g_w + (size_t)z * NM_ + (size_t)(brow + arow) * 1024 + acol;
    const int vrow = tid >> 5;
    const int vcl  = (tid & 31) * 2;
    const float* Bp = g_kv + (size_t)b * M_ * 2048 + 1024 + h * 64 + (size_t)vrow * 2048 + vcl;

    const int tx = tid & 15;
    const int ty = tid >> 4;

    float acc[8][4];
#pragma unroll
    for (int i = 0; i < 8; ++i)
#pragma unroll
        for (int j = 0; j < 4; ++j) acc[i][j] = 0.f;

    float4 a_reg = *(const float4*)(Ap);
    float2 b_reg = *(const float2*)(Bp);
    int buf = 0;
    As[0][(acol + 0) * AS + arow] = a_reg.x;
    As[0][(acol + 1) * AS + arow] = a_reg.y;
    As[0][(acol + 2) * AS + arow] = a_reg.z;
    As[0][(acol + 3) * AS + arow] = a_reg.w;
    *(float2*)&Bs[0][vrow * 64 + vcl] = b_reg;
    __syncthreads();

    for (int kt = 0; kt < NT; ++kt) {
        if (kt + 1 < NT) {
            a_reg = *(const float4*)(Ap + (kt + 1) * 8);
            b_reg = *(const float2*)(Bp + (size_t)(kt + 1) * 8 * 2048);
        }
#pragma unroll
        for (int k = 0; k < 8; ++k) {
            float4 a0 = *(const float4*)&As[buf][k * AS + ty * 4];
            float4 a1 = *(const float4*)&As[buf][k * AS + 64 + ty * 4];
            float4 b0 = *(const float4*)&Bs[buf][k * 64 + tx * 4];
            float ar[8] = {a0.x, a0.y, a0.z, a0.w, a1.x, a1.y, a1.z, a1.w};
#pragma unroll
            for (int i = 0; i < 8; ++i) {
                acc[i][0] = fmaf(ar[i], b0.x, acc[i][0]);
                acc[i][1] = fmaf(ar[i], b0.y, acc[i][1]);
                acc[i][2] = fmaf(ar[i], b0.z, acc[i][2]);
                acc[i][3] = fmaf(ar[i], b0.w, acc[i][3]);
            }
        }
        if (kt + 1 < NT) {
            buf ^= 1;
            As[buf][(acol + 0) * AS + arow] = a_reg.x;
            As[buf][(acol + 1) * AS + arow] = a_reg.y;
            As[buf][(acol + 2) * AS + arow] = a_reg.z;
            As[buf][(acol + 3) * AS + arow] = a_reg.w;
            *(float2*)&Bs[buf][vrow * 64 + vcl] = b_reg;
            __syncthreads();
        }
    }

#pragma unroll
    for (int ih = 0; ih < 2; ++ih)
#pragma unroll
        for (int i = 0; i < 4; ++i) {
            const int r = brow + ih * 64 + ty * 4 + i;
            float* Cp = out + (size_t)(b * 1024 + r) * 1024 + h * 64 + tx * 4;
            const int ai = ih * 4 + i;
            *(float4*)Cp = make_float4(acc[ai][0], acc[ai][1], acc[ai][2], acc[ai][3]);
        }
}

// ---------------------------------------------------------------------------
extern "C" void kernel_launch(void* const* d_in, const int* in_sizes, int n_in,
                              void* d_out, int out_size) {
    (void)in_sizes; (void)n_in; (void)out_size;
    const float* x     = (const float*)d_in[0];
    const float* ctx   = (const float*)d_in[1];
    const float* Wq    = (const float*)d_in[2];
    const float* Wkv   = (const float*)d_in[3];
    const float* Wt    = (const float*)d_in[4];
    const float* gamma = (const float*)d_in[5];
    const float* beta  = (const float*)d_in[6];
    float* out = (float*)d_out;

    proj_kernel<1024><<<dim3(1024 / 128, (B_ * N_) / 128), 256>>>(x, Wq);
    proj_kernel<2048><<<dim3(2048 / 128, (B_ * M_) / 128), 256>>>(ctx, Wkv);
    dots_kernel<<<dim3(M_ / 128, N_ / 128, B_ * H_), 256>>>();
    softmax_kernel<<<(B_ * H_ * N_) / 8, 256>>>();
    talking_kernel<<<(unsigned)((B_ * NM_) / 256), 256>>>(Wt, gamma, beta);
    attnv_kernel<<<dim3(1, N_ / 128, B_ * H_), 256>>>(out);
}

// round 10
// speedup vs baseline: 2.0325x; 2.0313x over previous
#include <cuda_runtime.h>
#include <cuda_bf16.h>
#include <cstdint>

using bf16 = __nv_bfloat16;

// CrossAttention B=4, N=M=1024, DIM=1024, H=16, d=vd=64.
// All GEMMs: warp-level HMMA (mma.sync bf16, sm_80-baseline PTX -> works on the
// harness's non-'a' sm_103 target) with bf16x3 split precision, fp32 accum.

// ---------------------------------------------------------------- scratch
__device__ __align__(16) bf16 g_xhi[4194304], g_xlo[4194304];     // x split
__device__ __align__(16) bf16 g_chi[4194304], g_clo[4194304];     // ctx split
__device__ __align__(16) bf16 g_wqhi[1048576], g_wqlo[1048576];   // Wq^T  [out][in]
__device__ __align__(16) bf16 g_wkhi[2097152], g_wklo[2097152];   // Wkv^T [out][in]
__device__ __align__(16) bf16 g_qhi[4194304], g_qlo[4194304];     // q*0.125 [b*N+i][h*64+d]
__device__ __align__(16) bf16 g_khi[4194304], g_klo[4194304];     // k       [b*M+j][h*64+d]
__device__ __align__(16) bf16 g_vthi[4194304], g_vtlo[4194304];   // v^T [b][h*64+vd][j]
__device__ float g_w[67108864];                                   // scores fp32 [b,h,i,j]
__device__ __align__(16) bf16 g_whi[67108864], g_wlo[67108864];   // post-softtalk w split

// ---------------------------------------------------------------- helpers
__device__ __forceinline__ uint32_t smem_u32(const void* p) {
    uint32_t a;
    asm("{ .reg .u64 t; cvta.to.shared.u64 t, %1; cvt.u32.u64 %0, t; }" : "=r"(a) : "l"(p));
    return a;
}
__device__ __forceinline__ void split2(float v, unsigned short& h, unsigned short& l) {
    bf16 hb = __float2bfloat16(v);
    h = __bfloat16_as_ushort(hb);
    l = __bfloat16_as_ushort(__float2bfloat16(v - __bfloat162float(hb)));
}
#define SWZ(x) ((x) ^ (((x) >> 3) & 0x70))

__device__ __forceinline__ void cpa16(uint32_t dst, const void* src) {
    asm volatile("cp.async.cg.shared.global [%0], [%1], 16;" :: "r"(dst), "l"(src));
}
__device__ __forceinline__ void ldsm4(uint32_t r[4], uint32_t addr) {
    asm volatile("ldmatrix.sync.aligned.m8n8.x4.shared.b16 {%0,%1,%2,%3}, [%4];"
                 : "=r"(r[0]), "=r"(r[1]), "=r"(r[2]), "=r"(r[3]) : "r"(addr));
}
__device__ __forceinline__ void mma_bf16(float c[4], const uint32_t a[4], const uint32_t b[2]) {
    asm volatile(
        "mma.sync.aligned.m16n8k16.row.col.f32.bf16.bf16.f32 "
        "{%0,%1,%2,%3}, {%4,%5,%6,%7}, {%8,%9}, {%0,%1,%2,%3};"
        : "+f"(c[0]), "+f"(c[1]), "+f"(c[2]), "+f"(c[3])
        : "r"(a[0]), "r"(a[1]), "r"(a[2]), "r"(a[3]), "r"(b[0]), "r"(b[1]));
}

// ---------------------------------------------------------------- prep kernels
__global__ __launch_bounds__(256) void split_kernel(const float* __restrict__ s,
                                                    bf16* __restrict__ hi, bf16* __restrict__ lo) {
    size_t i = (size_t)blockIdx.x * 256 + threadIdx.x;
    float4 v = ((const float4*)s)[i];
    unsigned short hh[4], ll[4];
    split2(v.x, hh[0], ll[0]); split2(v.y, hh[1], ll[1]);
    split2(v.z, hh[2], ll[2]); split2(v.w, hh[3], ll[3]);
    ((uint2*)hi)[i] = *(uint2*)hh;
    ((uint2*)lo)[i] = *(uint2*)ll;
}

__global__ void tsplit_kernel(const float* __restrict__ s, bf16* __restrict__ hi,
                              bf16* __restrict__ lo, int R, int C) {
    __shared__ float t[32][33];
    const int c0 = blockIdx.x * 32, r0 = blockIdx.y * 32;
    const int tx = threadIdx.x, ty = threadIdx.y;
#pragma unroll
    for (int k = 0; k < 4; ++k)
        t[ty + 8 * k][tx] = s[(size_t)(r0 + ty + 8 * k) * C + c0 + tx];
    __syncthreads();
#pragma unroll
    for (int k = 0; k < 4; ++k) {
        unsigned short h, l;
        split2(t[tx][ty + 8 * k], h, l);
        const size_t o = (size_t)(c0 + ty + 8 * k) * R + r0 + tx;
        hi[o] = __ushort_as_bfloat16(h);
        lo[o] = __ushort_as_bfloat16(l);
    }
}

// ---------------------------------------------------------------- HMMA GEMM
// C[128 x BN] per CTA = sum_k A[m][k]*B[n][k]  (A,B K-major bf16 hi/lo planes),
// bf16x3: hi*hi + hi*lo + lo*hi, fp32 accumulators.
// Per-z offsets: (z>>4)*S1 + (z&15)*S2 elements.
template<int BN, int KDIM, bool SPLIT_OUT>
__global__ __launch_bounds__(256)
void hmma_gemm(const bf16* __restrict__ Ahi, const bf16* __restrict__ Alo,
               int64_t aS1, int64_t aS2, int64_t lda,
               const bf16* __restrict__ Bhi, const bf16* __restrict__ Blo,
               int64_t bS1, int64_t bS2, int64_t ldb,
               float* __restrict__ Cf, bf16* __restrict__ Chi, bf16* __restrict__ Clo,
               int64_t cS1, int64_t cS2, int64_t ldc, float scale)
{
    constexpr int NC    = KDIM / 64;
    constexpr int ASTG  = 128 * 128;            // bytes per A plane (128 rows x 128B)
    constexpr int BSTG  = BN * 128;
    constexpr int STAGE = 2 * ASTG + 2 * BSTG;
    constexpr int NWN   = BN / 4;               // warp n-extent (32 or 16)
    constexpr int NFRAG = BN / 32;              // n-frags per warp (4 or 2)

    extern __shared__ char smem[];
    const uint32_t sb = smem_u32(smem);
    const int tid = threadIdx.x, lane = tid & 31, wid = tid >> 5;
    const int wm = wid >> 2, wn = wid & 3;

    const int z = blockIdx.z;
    const int64_t aB = (int64_t)(z >> 4) * aS1 + (int64_t)(z & 15) * aS2
                     + (int64_t)blockIdx.y * 128 * lda;
    const int64_t bB = (int64_t)(z >> 4) * bS1 + (int64_t)(z & 15) * bS2
                     + (int64_t)blockIdx.x * BN * ldb;
    const int64_t cB = (int64_t)(z >> 4) * cS1 + (int64_t)(z & 15) * cS2
                     + (int64_t)blockIdx.y * 128 * ldc + (int64_t)blockIdx.x * BN;

    float cf[4][NFRAG][4];
#pragma unroll
    for (int mf = 0; mf < 4; ++mf)
#pragma unroll
        for (int nf = 0; nf < NFRAG; ++nf)
#pragma unroll
            for (int q = 0; q < 4; ++q) cf[mf][nf][q] = 0.f;

    auto issue = [&](int c) {
        const uint32_t so = sb + (c & 1) * STAGE;
        const bf16* ah = Ahi + aB + c * 64;
        const bf16* al = Alo + aB + c * 64;
#pragma unroll
        for (int s = tid; s < 1024; s += 256) {             // A: 128 rows x 8 segs(16B)
            const int r = s >> 3, g = s & 7;
            const uint32_t sw = SWZ(r * 128 + g * 16);
            const int64_t go = (int64_t)r * lda + g * 8;
            cpa16(so + sw, ah + go);
            cpa16(so + ASTG + sw, al + go);
        }
        const bf16* bh = Bhi + bB + c * 64;
        const bf16* bl = Blo + bB + c * 64;
#pragma unroll
        for (int s = tid; s < BN * 8; s += 256) {           // B: BN rows x 8 segs
            const int r = s >> 3, g = s & 7;
            const uint32_t sw = SWZ(r * 128 + g * 16);
            const int64_t go = (int64_t)r * ldb + g * 8;
            cpa16(so + 2 * ASTG + sw, bh + go);
            cpa16(so + 2 * ASTG + BSTG + sw, bl + go);
        }
        asm volatile("cp.async.commit_group;" ::: "memory");
    };

    const int l8 = lane & 7, sub = lane >> 3;
    const int arow = wm * 64 + l8 + (sub & 1) * 8;          // + mf*16
    const int asegsel = sub >> 1;
    const int brow = wn * NWN + l8 + (sub >> 1) * 8;        // + nb*8
    const int bsegsel = sub & 1;

    auto compute = [&](int c) {
        const uint32_t sA  = sb + (c & 1) * STAGE;
        const uint32_t sBh = sA + 2 * ASTG;
#pragma unroll
        for (int kk = 0; kk < 4; ++kk) {
            uint32_t af[2][4][4];
#pragma unroll
            for (int mf = 0; mf < 4; ++mf) {
                const uint32_t ad = sA + SWZ((arow + mf * 16) * 128 + (kk * 2 + asegsel) * 16);
                ldsm4(af[0][mf], ad);
                ldsm4(af[1][mf], ad + ASTG);
            }
            uint32_t bfr[2][NFRAG][2];
#pragma unroll
            for (int nb = 0; nb < NFRAG; nb += 2) {
                const uint32_t bd = SWZ((brow + nb * 8) * 128 + (kk * 2 + bsegsel) * 16);
                uint32_t t[4];
                ldsm4(t, sBh + bd);
                bfr[0][nb][0] = t[0]; bfr[0][nb][1] = t[1];
                bfr[0][nb + 1][0] = t[2]; bfr[0][nb + 1][1] = t[3];
                ldsm4(t, sBh + BSTG + bd);
                bfr[1][nb][0] = t[0]; bfr[1][nb][1] = t[1];
                bfr[1][nb + 1][0] = t[2]; bfr[1][nb + 1][1] = t[3];
            }
#pragma unroll
            for (int mf = 0; mf < 4; ++mf)
#pragma unroll
                for (int nf = 0; nf < NFRAG; ++nf) {
                    mma_bf16(cf[mf][nf], af[0][mf], bfr[0][nf]);   // hi*hi
                    mma_bf16(cf[mf][nf], af[0][mf], bfr[1][nf]);   // hi*lo
                    mma_bf16(cf[mf][nf], af[1][mf], bfr[0][nf]);   // lo*hi
                }
        }
    };

    issue(0);
    if (NC > 1) issue(1);
    for (int c = 0; c < NC; ++c) {
        if (c + 1 < NC) asm volatile("cp.async.wait_group 1;" ::: "memory");
        else            asm volatile("cp.async.wait_group 0;" ::: "memory");
        __syncthreads();
        compute(c);
        __syncthreads();
        if (c + 2 < NC) issue(c + 2);
    }

    const int crow0 = wm * 64 + lane / 4;
    const int ccol0 = wn * NWN + (lane % 4) * 2;
#pragma unroll
    for (int mf = 0; mf < 4; ++mf)
#pragma unroll
        for (int nf = 0; nf < NFRAG; ++nf) {
            const int64_t o0 = cB + (int64_t)(crow0 + mf * 16) * ldc + ccol0 + nf * 8;
            const int64_t o1 = o0 + 8 * ldc;
            if constexpr (SPLIT_OUT) {
                unsigned short h0, l0, h1, l1;
                split2(cf[mf][nf][0] * scale, h0, l0);
                split2(cf[mf][nf][1] * scale, h1, l1);
                *(uint32_t*)&Chi[o0] = (uint32_t)h0 | ((uint32_t)h1 << 16);
                *(uint32_t*)&Clo[o0] = (uint32_t)l0 | ((uint32_t)l1 << 16);
                split2(cf[mf][nf][2] * scale, h0, l0);
                split2(cf[mf][nf][3] * scale, h1, l1);
                *(uint32_t*)&Chi[o1] = (uint32_t)h0 | ((uint32_t)h1 << 16);
                *(uint32_t*)&Clo[o1] = (uint32_t)l0 | ((uint32_t)l1 << 16);
            } else {
                *(float2*)&Cf[o0] = make_float2(cf[mf][nf][0], cf[mf][nf][1]);
                *(float2*)&Cf[o1] = make_float2(cf[mf][nf][2], cf[mf][nf][3]);
            }
        }
}

// ---------------------------------------------------------------- softmax + talking heads + LN
// One block per (b,i): 16 heads x 1024 j. Reads g_w fp32, writes g_whi/g_wlo bf16 split.
__global__ __launch_bounds__(256) void softtalk_kernel(
    const float* __restrict__ Wt, const float* __restrict__ gamma, const float* __restrict__ beta)
{
    extern __shared__ float sm[];        // [0:256) Wt, [256:272) gamma, [288:304) beta, rows @512
    float* rows = sm + 512;              // 16 rows x 1028
    const int tid = threadIdx.x;
    sm[tid] = Wt[tid];
    if (tid < 16) { sm[256 + tid] = gamma[tid]; sm[288 + tid] = beta[tid]; }
    const int b = blockIdx.x >> 10, i = blockIdx.x & 1023;
    const size_t base = ((size_t)b * 16) << 20;
    const size_t irow = (size_t)i * 1024;
#pragma unroll
    for (int h = 0; h < 16; ++h)
        *(float4*)(rows + h * 1028 + tid * 4) =
            *(const float4*)(g_w + base + ((size_t)h << 20) + irow + tid * 4);
    __syncthreads();

    const int wid = tid >> 5, lane = tid & 31;
#pragma unroll
    for (int rr = wid; rr < 16; rr += 8) {
        float* r = rows + rr * 1028;
        float mx = -1e30f;
        for (int j = lane; j < 1024; j += 32) mx = fmaxf(mx, r[j]);
#pragma unroll
        for (int o = 16; o; o >>= 1) mx = fmaxf(mx, __shfl_xor_sync(~0u, mx, o));
        float s = 0.f;
        for (int j = lane; j < 1024; j += 32) { float e = __expf(r[j] - mx); r[j] = e; s += e; }
#pragma unroll
        for (int o = 16; o; o >>= 1) s += __shfl_xor_sync(~0u, s, o);
        const float inv = 1.f / s;
        for (int j = lane; j < 1024; j += 32) r[j] *= inv;
    }
    __syncthreads();

#pragma unroll
    for (int jj = 0; jj < 4; ++jj) {
        const int j = tid + jj * 256;
        float o[16];
#pragma unroll
        for (int g = 0; g < 16; ++g) o[g] = 0.f;
#pragma unroll
        for (int h = 0; h < 16; ++h) {
            const float v = rows[h * 1028 + j];
#pragma unroll
            for (int g = 0; g < 16; ++g) o[g] = fmaf(v, sm[h * 16 + g], o[g]);
        }
        float mu = 0.f;
#pragma unroll
        for (int g = 0; g < 16; ++g) mu += o[g];
        mu *= 0.0625f;
        float var = 0.f;
#pragma unroll
        for (int g = 0; g < 16; ++g) { const float dd = o[g] - mu; var = fmaf(dd, dd, var); }
        var *= 0.0625f;
        const float rstd = rsqrtf(var + 1e-5f);
#pragma unroll
        for (int g = 0; g < 16; ++g) {
            const float val = (o[g] - mu) * rstd * sm[256 + g] + sm[288 + g];
            unsigned short h16, l16;
            split2(val, h16, l16);
            const size_t oo = base + ((size_t)g << 20) + irow + j;
            g_whi[oo] = __ushort_as_bfloat16(h16);
            g_wlo[oo] = __ushort_as_bfloat16(l16);
        }
    }
}

// ---------------------------------------------------------------- launch
extern "C" void kernel_launch(void* const* d_in, const int* in_sizes, int n_in,
                              void* d_out, int out_size) {
    (void)in_sizes; (void)n_in; (void)out_size;
    const float* x   = (const float*)d_in[0];
    const float* ctx = (const float*)d_in[1];
    const float* Wq  = (const float*)d_in[2];
    const float* Wkv = (const float*)d_in[3];
    const float* Wt  = (const float*)d_in[4];
    const float* gm  = (const float*)d_in[5];
    const float* bt  = (const float*)d_in[6];
    float* out = (float*)d_out;

    bf16 *xhi, *xlo, *chi, *clo, *wqh, *wql, *wkh, *wkl;
    bf16 *qh, *ql, *kh, *kl, *vth, *vtl, *whi, *wlo;
    float* gw;
    cudaGetSymbolAddress((void**)&xhi, g_xhi);   cudaGetSymbolAddress((void**)&xlo, g_xlo);
    cudaGetSymbolAddress((void**)&chi, g_chi);   cudaGetSymbolAddress((void**)&clo, g_clo);
    cudaGetSymbolAddress((void**)&wqh, g_wqhi);  cudaGetSymbolAddress((void**)&wql, g_wqlo);
    cudaGetSymbolAddress((void**)&wkh, g_wkhi);  cudaGetSymbolAddress((void**)&wkl, g_wklo);
    cudaGetSymbolAddress((void**)&qh,  g_qhi);   cudaGetSymbolAddress((void**)&ql,  g_qlo);
    cudaGetSymbolAddress((void**)&kh,  g_khi);   cudaGetSymbolAddress((void**)&kl,  g_klo);
    cudaGetSymbolAddress((void**)&vth, g_vthi);  cudaGetSymbolAddress((void**)&vtl, g_vtlo);
    cudaGetSymbolAddress((void**)&whi, g_whi);   cudaGetSymbolAddress((void**)&wlo, g_wlo);
    cudaGetSymbolAddress((void**)&gw,  g_w);

    constexpr int SMEM_128 = 2 * (2 * 16384 + 2 * 16384);   // 131072
    constexpr int SMEM_DOT = (2 * 16384 + 2 * 16384);       // 65536 (single stage)
    constexpr int SMEM_64  = 2 * (2 * 16384 + 2 * 8192);    // 98304
    constexpr int SST      = (512 + 16 * 1028) * 4;         // 67840
    cudaFuncSetAttribute(hmma_gemm<128, 1024, true >, cudaFuncAttributeMaxDynamicSharedMemorySize, SMEM_128);
    cudaFuncSetAttribute(hmma_gemm<128,   64, false>, cudaFuncAttributeMaxDynamicSharedMemorySize, SMEM_DOT);
    cudaFuncSetAttribute(hmma_gemm< 64, 1024, false>, cudaFuncAttributeMaxDynamicSharedMemorySize, SMEM_64);
    cudaFuncSetAttribute(softtalk_kernel,             cudaFuncAttributeMaxDynamicSharedMemorySize, SST);

    const int64_t M20 = 1 << 20;

    split_kernel<<<4096, 256>>>(x, xhi, xlo);
    split_kernel<<<4096, 256>>>(ctx, chi, clo);
    tsplit_kernel<<<dim3(32, 32), dim3(32, 8)>>>(Wq,  wqh, wql, 1024, 1024);
    tsplit_kernel<<<dim3(64, 32), dim3(32, 8)>>>(Wkv, wkh, wkl, 1024, 2048);

    // q = 0.125 * x @ Wq        [4096 x 1024 x 1024]
    hmma_gemm<128, 1024, true><<<dim3(8, 32, 1), 256, SMEM_128>>>(
        xhi, xlo, 0, 0, 1024,  wqh, wql, 0, 0, 1024,
        nullptr, qh, ql, 0, 0, 1024, 0.125f);
    // k = ctx @ Wkv[:, :1024]   [4096 x 1024 x 1024]
    hmma_gemm<128, 1024, true><<<dim3(8, 32, 1), 256, SMEM_128>>>(
        chi, clo, 0, 0, 1024,  wkh, wkl, 0, 0, 1024,
        nullptr, kh, kl, 0, 0, 1024, 1.f);
    // vt[b][h*64+vd][j] = Wkv_v^T @ ctx_b^T   (4 batches of 1024 x 1024 x 1024)
    hmma_gemm<128, 1024, true><<<dim3(8, 8, 4), 256, SMEM_128>>>(
        wkh + M20, wkl + M20, 0, 0, 1024,  chi, clo, 0, M20, 1024,
        nullptr, vth, vtl, 0, M20, 1024, 1.f);
    // dots: per (b,h) 1024 x 1024 x 64 -> g_w fp32
    hmma_gemm<128, 64, false><<<dim3(8, 8, 64), 256, SMEM_DOT>>>(
        qh, ql, M20, 64, 1024,  kh, kl, M20, 64, 1024,
        gw, nullptr, nullptr, 16 * M20, M20, 1024, 1.f);
    // softmax + talking + LN -> g_whi/g_wlo
    softtalk_kernel<<<4096, 256, SST>>>(Wt, gm, bt);
    // out = w @ v : per (b,h) 1024 x 64 x 1024, scattered into d_out
    hmma_gemm<64, 1024, false><<<dim3(1, 8, 64), 256, SMEM_64>>>(
        whi, wlo, 16 * M20, M20, 1024,  vth, vtl, M20, 65536, 1024,
        out, nullptr, nullptr, M20, 64, 1024, 1.f);
}